// round 2
// baseline (speedup 1.0000x reference)
#include <cuda_runtime.h>

#define B_  16
#define S_  2048
#define D_  128
#define BQ  64
#define BK  64
#define NT  256

#define QS_STR 128   // q tile row stride (floats)
#define KT_STR 68    // transposed k tile row stride (floats), 16B-aligned rows
#define VS_STR 128   // v tile row stride
#define SS_STR 68    // score tile row stride

#define SMEM_FLOATS (BQ*QS_STR + D_*KT_STR + BK*VS_STR + BQ*SS_STR + 3*BQ + 16)

__global__ __launch_bounds__(NT, 1)
void fa_kernel(const float* __restrict__ Q, const float* __restrict__ K,
               const float* __restrict__ V, const unsigned char* __restrict__ kpm,
               const int* __restrict__ cls, float* __restrict__ O)
{
    extern __shared__ float sm[];
    float* qs   = sm;                      // [BQ][QS_STR]
    float* kt   = qs + BQ*QS_STR;          // [D_][KT_STR]  kt[d][key]
    float* vs   = kt + D_*KT_STR;          // [BK][VS_STR]
    float* ss   = vs + BK*VS_STR;          // [BQ][SS_STR]
    float* mrow = ss + BQ*SS_STR;          // [BQ]
    float* lrow = mrow + BQ;               // [BQ]
    float* arow = lrow + BQ;               // [BQ]
    unsigned char* kpms = (unsigned char*)(arow + BQ);  // [BK]

    const int tid = threadIdx.x;
    const int b  = blockIdx.y;
    const int q0 = blockIdx.x * BQ;

    const int i0 = cls[b*3 + 0];
    const int i1 = cls[b*3 + 1];
    const int i2 = cls[b*3 + 2];
    const float scale = 0.08838834764831845f;   // 1/sqrt(128)

    const int ty = tid >> 4;   // 0..15  q-row group (QK and PV)
    const int tx = tid & 15;   // 0..15  key group (QK) / d-col group (PV)

    // ---- load Q tile (float4, fully coalesced) ----
    {
        const float4* Qb = reinterpret_cast<const float4*>(Q + ((size_t)b*S_ + q0)*D_);
        float4* qs4 = reinterpret_cast<float4*>(qs);
        #pragma unroll
        for (int it = 0; it < (BQ*D_/4)/NT; ++it)
            qs4[tid + it*NT] = Qb[tid + it*NT];
    }
    if (tid < BQ) { mrow[tid] = -1e30f; lrow[tid] = 0.0f; }

    float acc[4][8];
    #pragma unroll
    for (int i = 0; i < 4; ++i)
        #pragma unroll
        for (int j = 0; j < 8; ++j) acc[i][j] = 0.0f;

    for (int kb = 0; kb < S_; kb += BK) {
        __syncthreads();   // protect kt/vs/ss from previous iteration's readers

        // ---- load K transposed: kt[c][r] = K[kb+r][c] ----
        // idx -> r4 = idx>>7 (row group of 4), c = idx&127.
        // reads: lanes sweep c -> coalesced 128B; write: LDS.128 conflict-free.
        {
            const float* Kb = K + ((size_t)b*S_ + kb)*D_;
            #pragma unroll
            for (int it = 0; it < (BK*D_/4)/NT; ++it) {
                int idx = tid + it*NT;
                int c  = idx & (D_-1);
                int r4 = idx >> 7;          // 0..15
                float4 v;
                v.x = Kb[(r4*4+0)*D_ + c];
                v.y = Kb[(r4*4+1)*D_ + c];
                v.z = Kb[(r4*4+2)*D_ + c];
                v.w = Kb[(r4*4+3)*D_ + c];
                *reinterpret_cast<float4*>(&kt[c*KT_STR + r4*4]) = v;
            }
        }
        // ---- load V tile (float4 coalesced) ----
        {
            const float4* Vb = reinterpret_cast<const float4*>(V + ((size_t)b*S_ + kb)*D_);
            float4* vs4 = reinterpret_cast<float4*>(vs);
            #pragma unroll
            for (int it = 0; it < (BK*D_/4)/NT; ++it)
                vs4[tid + it*NT] = Vb[tid + it*NT];
        }
        if (tid < BK) kpms[tid] = kpm[(size_t)b*S_ + kb + tid];
        __syncthreads();

        // ---- QK^T : 4x4 scores per thread ----
        float s[4][4];
        #pragma unroll
        for (int i = 0; i < 4; ++i)
            #pragma unroll
            for (int j = 0; j < 4; ++j) s[i][j] = 0.0f;

        #pragma unroll 4
        for (int d = 0; d < D_; d += 4) {
            float a[4][4], kk[4][4];
            #pragma unroll
            for (int i = 0; i < 4; ++i)
                *reinterpret_cast<float4*>(a[i]) =
                    *reinterpret_cast<const float4*>(&qs[(ty*4+i)*QS_STR + d]);
            #pragma unroll
            for (int dd = 0; dd < 4; ++dd)
                *reinterpret_cast<float4*>(kk[dd]) =
                    *reinterpret_cast<const float4*>(&kt[(d+dd)*KT_STR + tx*4]);
            #pragma unroll
            for (int dd = 0; dd < 4; ++dd)
                #pragma unroll
                for (int i = 0; i < 4; ++i)
                    #pragma unroll
                    for (int j = 0; j < 4; ++j)
                        s[i][j] += a[i][dd] * kk[dd][j];
        }

        // ---- mask + store scores (float4) ----
        #pragma unroll
        for (int i = 0; i < 4; ++i) {
            int rg = q0 + ty*4 + i;
            bool isr1 = (rg == i1);
            bool isr2 = (rg == i2);
            float4 sv;
            float t[4];
            #pragma unroll
            for (int j = 0; j < 4; ++j) {
                int jl = tx*4 + j;
                int jg = kb + jl;
                float v = s[i][j] * scale;
                bool msk = (kpms[jl] != 0)
                        || (isr1 && (((jg > i1) && (jg <= i2)) || (jg == 0)))
                        || (isr2 && (((jg > i0) && (jg <= i1)) || (jg == 0)));
                t[j] = msk ? -1e30f : v;
            }
            sv.x = t[0]; sv.y = t[1]; sv.z = t[2]; sv.w = t[3];
            *reinterpret_cast<float4*>(&ss[(ty*4+i)*SS_STR + tx*4]) = sv;
        }
        __syncthreads();

        // ---- online softmax: 4 threads per row ----
        {
            int r2 = tid >> 2;
            int sg = tid & 3;
            float vals[16];
            #pragma unroll
            for (int c4 = 0; c4 < 4; ++c4) {
                float4 vq = *reinterpret_cast<const float4*>(&ss[r2*SS_STR + sg*16 + c4*4]);
                vals[c4*4+0] = vq.x; vals[c4*4+1] = vq.y;
                vals[c4*4+2] = vq.z; vals[c4*4+3] = vq.w;
            }
            float lm = -1e30f;
            #pragma unroll
            for (int c = 0; c < 16; ++c) lm = fmaxf(lm, vals[c]);
            lm = fmaxf(lm, __shfl_xor_sync(0xffffffffu, lm, 1));
            lm = fmaxf(lm, __shfl_xor_sync(0xffffffffu, lm, 2));
            float mold = mrow[r2];
            float mnew = fmaxf(mold, lm);
            float lsum = 0.0f;
            #pragma unroll
            for (int c = 0; c < 16; ++c) {
                float p = __expf(vals[c] - mnew);
                vals[c] = p;
                lsum += p;
            }
            #pragma unroll
            for (int c4 = 0; c4 < 4; ++c4) {
                float4 vq;
                vq.x = vals[c4*4+0]; vq.y = vals[c4*4+1];
                vq.z = vals[c4*4+2]; vq.w = vals[c4*4+3];
                *reinterpret_cast<float4*>(&ss[r2*SS_STR + sg*16 + c4*4]) = vq;
            }
            lsum += __shfl_xor_sync(0xffffffffu, lsum, 1);
            lsum += __shfl_xor_sync(0xffffffffu, lsum, 2);
            __syncwarp();
            if (sg == 0) {
                float al = __expf(mold - mnew);
                arow[r2] = al;
                mrow[r2] = mnew;
                lrow[r2] = lrow[r2]*al + lsum;
            }
        }
        __syncthreads();

        // ---- rescale accumulators, then P·V ----
        #pragma unroll
        for (int i = 0; i < 4; ++i) {
            float al = arow[ty*4 + i];
            #pragma unroll
            for (int j = 0; j < 8; ++j) acc[i][j] *= al;
        }
        #pragma unroll 4
        for (int k4 = 0; k4 < BK; k4 += 4) {
            float p[4][4];
            #pragma unroll
            for (int i = 0; i < 4; ++i)
                *reinterpret_cast<float4*>(p[i]) =
                    *reinterpret_cast<const float4*>(&ss[(ty*4+i)*SS_STR + k4]);
            #pragma unroll
            for (int kk2 = 0; kk2 < 4; ++kk2) {
                float4 v0 = *reinterpret_cast<const float4*>(&vs[(k4+kk2)*VS_STR + tx*4]);
                float4 v1 = *reinterpret_cast<const float4*>(&vs[(k4+kk2)*VS_STR + 64 + tx*4]);
                #pragma unroll
                for (int i = 0; i < 4; ++i) {
                    float pv = p[i][kk2];
                    acc[i][0] += pv * v0.x; acc[i][1] += pv * v0.y;
                    acc[i][2] += pv * v0.z; acc[i][3] += pv * v0.w;
                    acc[i][4] += pv * v1.x; acc[i][5] += pv * v1.y;
                    acc[i][6] += pv * v1.z; acc[i][7] += pv * v1.w;
                }
            }
        }
    }

    // ---- normalize and write out ----
    #pragma unroll
    for (int i = 0; i < 4; ++i) {
        float inv = 1.0f / lrow[ty*4 + i];
        int rg = q0 + ty*4 + i;
        float* Ob = O + ((size_t)b*S_ + rg)*D_;
        float4 o0, o1;
        o0.x = acc[i][0]*inv; o0.y = acc[i][1]*inv;
        o0.z = acc[i][2]*inv; o0.w = acc[i][3]*inv;
        o1.x = acc[i][4]*inv; o1.y = acc[i][5]*inv;
        o1.z = acc[i][6]*inv; o1.w = acc[i][7]*inv;
        *reinterpret_cast<float4*>(Ob + tx*4)      = o0;
        *reinterpret_cast<float4*>(Ob + 64 + tx*4) = o1;
    }
}

extern "C" void kernel_launch(void* const* d_in, const int* in_sizes, int n_in,
                              void* d_out, int out_size)
{
    const float* Q = (const float*)d_in[0];
    const float* K = (const float*)d_in[1];
    const float* V = (const float*)d_in[2];
    const unsigned char* kpm = (const unsigned char*)d_in[3];
    const int* cls = (const int*)d_in[4];
    float* O = (float*)d_out;

    size_t smem = (size_t)SMEM_FLOATS * sizeof(float);
    cudaFuncSetAttribute(fa_kernel, cudaFuncAttributeMaxDynamicSharedMemorySize, (int)smem);

    dim3 grid(S_/BQ, B_);
    fa_kernel<<<grid, NT, smem>>>(Q, K, V, kpm, cls, O);
}

// round 3
// speedup vs baseline: 1.1921x; 1.1921x over previous
#include <cuda_runtime.h>

#define B_  16
#define S_  2048
#define D_  128
#define BQ  128
#define BK  64
#define NT  256

#define QS_STR 132   // q tile row stride (floats)
#define KT_STR 68    // transposed k tile row stride
#define VS_STR 132   // v tile row stride
#define PS_STR 68    // p tile row stride

#define SMEM_FLOATS (BQ*QS_STR + D_*KT_STR + BK*VS_STR + BQ*PS_STR + 32)

__global__ __launch_bounds__(NT, 1)
void fa_kernel(const float* __restrict__ Q, const float* __restrict__ K,
               const float* __restrict__ V, const unsigned char* __restrict__ kpm,
               const int* __restrict__ cls, float* __restrict__ O)
{
    extern __shared__ float sm[];
    float* qs = sm;                         // [BQ][QS_STR]
    float* kt = qs + BQ*QS_STR;             // [D_][KT_STR]   kt[d][key]
    float* vs = kt + D_*KT_STR;             // [BK][VS_STR]
    float* ps = vs + BK*VS_STR;             // [BQ][PS_STR]   exp'd probabilities
    unsigned char* kpms = (unsigned char*)(ps + BQ*PS_STR);   // [BK]

    const int tid = threadIdx.x;
    const int b  = blockIdx.y;
    const int q0 = blockIdx.x * BQ;

    const int i0 = cls[b*3 + 0];
    const int i1 = cls[b*3 + 1];
    const int i2 = cls[b*3 + 2];
    const float scale = 0.08838834764831845f;   // 1/sqrt(128)

    const int ty = tid >> 4;   // 0..15 : q rows [ty*8, ty*8+8)
    const int tx = tid & 15;   // 0..15 : keys tx*4 (QK) / out cols tx*8 (PV)

    // ---- load Q tile: coalesced f4, strided smem rows ----
    {
        const float4* Qb = reinterpret_cast<const float4*>(Q + ((size_t)b*S_ + q0)*D_);
        #pragma unroll
        for (int it = 0; it < (BQ*D_/4)/NT; ++it) {
            int idx = tid + it*NT;           // f4 index over [128][32]
            int r  = idx >> 5;
            int c4 = idx & 31;
            *reinterpret_cast<float4*>(&qs[r*QS_STR + c4*4]) = Qb[idx];
        }
    }

    // per-row online-softmax state, replicated across the row's 16 lanes
    float m[8], l[8];
    float acc[8][8];
    #pragma unroll
    for (int i = 0; i < 8; ++i) {
        m[i] = -1e30f; l[i] = 0.0f;
        #pragma unroll
        for (int j = 0; j < 8; ++j) acc[i][j] = 0.0f;
    }

    for (int kb = 0; kb < S_; kb += BK) {
        __syncthreads();   // previous tile's kt/vs/ps readers done

        // ---- K transposed: kt[c][r] = K[kb+r][c]; coalesced global reads ----
        {
            const float* Kb = K + ((size_t)b*S_ + kb)*D_;
            #pragma unroll
            for (int it = 0; it < (BK*D_/4)/NT; ++it) {
                int idx = tid + it*NT;
                int c  = idx & (D_-1);
                int r4 = idx >> 7;          // 0..15
                float4 v;
                v.x = Kb[(r4*4+0)*D_ + c];
                v.y = Kb[(r4*4+1)*D_ + c];
                v.z = Kb[(r4*4+2)*D_ + c];
                v.w = Kb[(r4*4+3)*D_ + c];
                *reinterpret_cast<float4*>(&kt[c*KT_STR + r4*4]) = v;
            }
        }
        // ---- V tile ----
        {
            const float4* Vb = reinterpret_cast<const float4*>(V + ((size_t)b*S_ + kb)*D_);
            #pragma unroll
            for (int it = 0; it < (BK*D_/4)/NT; ++it) {
                int idx = tid + it*NT;
                int r  = idx >> 5;
                int c4 = idx & 31;
                *reinterpret_cast<float4*>(&vs[r*VS_STR + c4*4]) = Vb[idx];
            }
        }
        if (tid < BK) kpms[tid] = kpm[(size_t)b*S_ + kb + tid];
        __syncthreads();

        // ---- QK^T : 8x4 scores per thread ----
        float s[8][4];
        #pragma unroll
        for (int i = 0; i < 8; ++i)
            #pragma unroll
            for (int j = 0; j < 4; ++j) s[i][j] = 0.0f;

        #pragma unroll 2
        for (int d = 0; d < D_; d += 4) {
            float a[8][4], kk[4][4];
            #pragma unroll
            for (int i = 0; i < 8; ++i)
                *reinterpret_cast<float4*>(a[i]) =
                    *reinterpret_cast<const float4*>(&qs[(ty*8+i)*QS_STR + d]);
            #pragma unroll
            for (int dd = 0; dd < 4; ++dd)
                *reinterpret_cast<float4*>(kk[dd]) =
                    *reinterpret_cast<const float4*>(&kt[(d+dd)*KT_STR + tx*4]);
            #pragma unroll
            for (int dd = 0; dd < 4; ++dd)
                #pragma unroll
                for (int i = 0; i < 8; ++i)
                    #pragma unroll
                    for (int j = 0; j < 4; ++j)
                        s[i][j] += a[i][dd] * kk[dd][j];
        }

        // ---- scale + mask (in registers) ----
        uchar4 kp4 = reinterpret_cast<const uchar4*>(kpms)[tx];
        unsigned char kpl[4] = {kp4.x, kp4.y, kp4.z, kp4.w};
        #pragma unroll
        for (int i = 0; i < 8; ++i) {
            int rg = q0 + ty*8 + i;
            bool isr1 = (rg == i1);
            bool isr2 = (rg == i2);
            #pragma unroll
            for (int j = 0; j < 4; ++j) {
                int jg = kb + tx*4 + j;
                float v = s[i][j] * scale;
                bool msk = (kpl[j] != 0)
                        || (isr1 && (((jg > i1) && (jg <= i2)) || (jg == 0)))
                        || (isr2 && (((jg > i0) && (jg <= i1)) || (jg == 0)));
                s[i][j] = msk ? -1e30f : v;
            }
        }

        // ---- in-register online softmax (row = 16 lanes of one warp half) ----
        #pragma unroll
        for (int i = 0; i < 8; ++i) {
            float mx = fmaxf(fmaxf(s[i][0], s[i][1]), fmaxf(s[i][2], s[i][3]));
            mx = fmaxf(mx, __shfl_xor_sync(0xffffffffu, mx, 1));
            mx = fmaxf(mx, __shfl_xor_sync(0xffffffffu, mx, 2));
            mx = fmaxf(mx, __shfl_xor_sync(0xffffffffu, mx, 4));
            mx = fmaxf(mx, __shfl_xor_sync(0xffffffffu, mx, 8));
            float mn = fmaxf(m[i], mx);
            float al = __expf(m[i] - mn);
            m[i] = mn;
            float sum = 0.0f;
            #pragma unroll
            for (int j = 0; j < 4; ++j) {
                float p = __expf(s[i][j] - mn);
                s[i][j] = p;
                sum += p;
            }
            sum += __shfl_xor_sync(0xffffffffu, sum, 1);
            sum += __shfl_xor_sync(0xffffffffu, sum, 2);
            sum += __shfl_xor_sync(0xffffffffu, sum, 4);
            sum += __shfl_xor_sync(0xffffffffu, sum, 8);
            l[i] = l[i]*al + sum;
            #pragma unroll
            for (int c = 0; c < 8; ++c) acc[i][c] *= al;
        }

        // ---- store P once for the PV redistribution ----
        #pragma unroll
        for (int i = 0; i < 8; ++i) {
            float4 sv;
            sv.x = s[i][0]; sv.y = s[i][1]; sv.z = s[i][2]; sv.w = s[i][3];
            *reinterpret_cast<float4*>(&ps[(ty*8+i)*PS_STR + tx*4]) = sv;
        }
        __syncthreads();

        // ---- P·V : 8x8 per thread ----
        #pragma unroll 2
        for (int k0 = 0; k0 < BK; k0 += 4) {
            float p[8][4];
            #pragma unroll
            for (int i = 0; i < 8; ++i)
                *reinterpret_cast<float4*>(p[i]) =
                    *reinterpret_cast<const float4*>(&ps[(ty*8+i)*PS_STR + k0]);
            #pragma unroll
            for (int kk2 = 0; kk2 < 4; ++kk2) {
                float4 v0 = *reinterpret_cast<const float4*>(&vs[(k0+kk2)*VS_STR + tx*8]);
                float4 v1 = *reinterpret_cast<const float4*>(&vs[(k0+kk2)*VS_STR + tx*8 + 4]);
                #pragma unroll
                for (int i = 0; i < 8; ++i) {
                    float pv = p[i][kk2];
                    acc[i][0] += pv * v0.x; acc[i][1] += pv * v0.y;
                    acc[i][2] += pv * v0.z; acc[i][3] += pv * v0.w;
                    acc[i][4] += pv * v1.x; acc[i][5] += pv * v1.y;
                    acc[i][6] += pv * v1.z; acc[i][7] += pv * v1.w;
                }
            }
        }
    }

    // ---- normalize and write out (l replicated in-register, no smem) ----
    #pragma unroll
    for (int i = 0; i < 8; ++i) {
        float inv = 1.0f / l[i];
        int rg = q0 + ty*8 + i;
        float* Ob = O + ((size_t)b*S_ + rg)*D_ + tx*8;
        float4 o0, o1;
        o0.x = acc[i][0]*inv; o0.y = acc[i][1]*inv;
        o0.z = acc[i][2]*inv; o0.w = acc[i][3]*inv;
        o1.x = acc[i][4]*inv; o1.y = acc[i][5]*inv;
        o1.z = acc[i][6]*inv; o1.w = acc[i][7]*inv;
        *reinterpret_cast<float4*>(Ob)     = o0;
        *reinterpret_cast<float4*>(Ob + 4) = o1;
    }
}

extern "C" void kernel_launch(void* const* d_in, const int* in_sizes, int n_in,
                              void* d_out, int out_size)
{
    const float* Q = (const float*)d_in[0];
    const float* K = (const float*)d_in[1];
    const float* V = (const float*)d_in[2];
    const unsigned char* kpm = (const unsigned char*)d_in[3];
    const int* cls = (const int*)d_in[4];
    float* O = (float*)d_out;

    size_t smem = (size_t)SMEM_FLOATS * sizeof(float);
    cudaFuncSetAttribute(fa_kernel, cudaFuncAttributeMaxDynamicSharedMemorySize, (int)smem);

    dim3 grid(S_/BQ, B_);
    fa_kernel<<<grid, NT, smem>>>(Q, K, V, kpm, cls, O);
}

// round 7
// speedup vs baseline: 3.4560x; 2.8991x over previous
#include <cuda_runtime.h>
#include <cuda_bf16.h>

#define B_  16
#define S_  2048
#define D_  128
#define BQ  128
#define BK  64
#define NT  256
#define NTILES (S_/BK)

#define STR 272              // smem row stride in bytes (128 bf16 + 8 pad)

#define OFF_QH 0
#define OFF_QL 34816
#define OFF_KH 69632
#define OFF_KL 87040
#define OFF_VH 104448
#define OFF_VL 121856
#define OFF_KPM 139264
#define SMEM_BYTES (139264 + 128)

__device__ __forceinline__ unsigned smem_u32(const void* p) {
    unsigned a;
    asm("{ .reg .u64 t; cvta.to.shared.u64 t, %1; cvt.u32.u64 %0, t; }" : "=r"(a) : "l"(p));
    return a;
}

#define LDSM_X4(r0,r1,r2,r3,a) \
    asm volatile("ldmatrix.sync.aligned.m8n8.x4.shared.b16 {%0,%1,%2,%3}, [%4];" \
                 : "=r"(r0),"=r"(r1),"=r"(r2),"=r"(r3) : "r"(a))
#define LDSM_X4T(r0,r1,r2,r3,a) \
    asm volatile("ldmatrix.sync.aligned.m8n8.x4.trans.shared.b16 {%0,%1,%2,%3}, [%4];" \
                 : "=r"(r0),"=r"(r1),"=r"(r2),"=r"(r3) : "r"(a))

#define MMA(c,a0,a1,a2,a3,b0,b1) \
    asm volatile("mma.sync.aligned.m16n8k16.row.col.f32.bf16.bf16.f32 " \
                 "{%0,%1,%2,%3}, {%4,%5,%6,%7}, {%8,%9}, {%0,%1,%2,%3};" \
                 : "+f"((c)[0]),"+f"((c)[1]),"+f"((c)[2]),"+f"((c)[3]) \
                 : "r"(a0),"r"(a1),"r"(a2),"r"(a3),"r"(b0),"r"(b1))

__device__ __forceinline__ unsigned pack2(float x, float y) {
    __nv_bfloat162 h = __floats2bfloat162_rn(x, y);   // x -> low half
    return *reinterpret_cast<unsigned*>(&h);
}

// split f32 -> (hi bf16, lo bf16) packed pairwise
__device__ __forceinline__ void split2(float x, float y, unsigned& hi, unsigned& lo) {
    __nv_bfloat16 hx = __float2bfloat16(x), hy = __float2bfloat16(y);
    float lx = x - __bfloat162float(hx);
    float ly = y - __bfloat162float(hy);
    __nv_bfloat162 hp; hp.x = hx; hp.y = hy;
    hi = *reinterpret_cast<unsigned*>(&hp);
    lo = pack2(lx, ly);
}

// cooperative load of [rows][128] f32 tile -> split bf16 hi/lo smem (stride 272B)
template<int ROWS>
__device__ __forceinline__ void load_split(char* smc, const float* g, int offH, int offL, float mul) {
    const float4* g4 = reinterpret_cast<const float4*>(g);
    #pragma unroll
    for (int it = 0; it < (ROWS * 32) / NT; ++it) {
        int idx = threadIdx.x + it * NT;
        int r = idx >> 5, c4 = idx & 31;
        float4 v = g4[idx];
        unsigned h0, l0, h1, l1;
        split2(v.x * mul, v.y * mul, h0, l0);
        split2(v.z * mul, v.w * mul, h1, l1);
        unsigned off = (unsigned)(r * STR + c4 * 8);
        *reinterpret_cast<uint2*>(smc + offH + off) = make_uint2(h0, h1);
        *reinterpret_cast<uint2*>(smc + offL + off) = make_uint2(l0, l1);
    }
}

__global__ __launch_bounds__(NT, 1)
void fa_mma_kernel(const float* __restrict__ Q, const float* __restrict__ K,
                   const float* __restrict__ V, const unsigned char* __restrict__ kpm,
                   const int* __restrict__ cls, float* __restrict__ O)
{
    extern __shared__ char smc[];
    const unsigned sb = smem_u32(smc);
    const int tid  = threadIdx.x;
    const int wid  = tid >> 5;
    const int lane = tid & 31;
    const int b  = blockIdx.y;
    const int q0 = blockIdx.x * BQ;

    const int i0 = cls[b*3 + 0];
    const int i1 = cls[b*3 + 1];
    const int i2 = cls[b*3 + 2];

    // this thread's two q-rows (within warp's 16-row block)
    const int rg0 = q0 + wid*16 + (lane >> 2);
    const int rg1 = rg0 + 8;
    const bool isr1_0 = (rg0 == i1), isr2_0 = (rg0 == i2);
    const bool isr1_1 = (rg1 == i1), isr2_1 = (rg1 == i2);

    // Q tile -> smem, pre-scaled by 1/sqrt(d)
    load_split<BQ>(smc, Q + ((size_t)b*S_ + q0)*D_, OFF_QH, OFF_QL, 0.08838834764831845f);

    float o[16][4];
    #pragma unroll
    for (int i = 0; i < 16; ++i)
        #pragma unroll
        for (int j = 0; j < 4; ++j) o[i][j] = 0.0f;
    float lsum0 = 0.0f, lsum1 = 0.0f;

    // per-warp ldmatrix lane addressing (byte offsets within a tile)
    const unsigned qrow_off = (unsigned)((wid*16 + (lane & 15)) * STR) + ((lane >> 4) ? 16u : 0u);
    const unsigned krow     = (unsigned)((((lane >> 4) & 1) * 8 + (lane & 7)) * STR) + (((lane >> 3) & 1) ? 16u : 0u);
    const unsigned vrow     = (unsigned)(((((lane >> 3) & 1) * 8) + (lane & 7)) * STR) + ((lane >> 4) ? 16u : 0u);

    for (int tl = 0; tl < NTILES; ++tl) {
        const int kb = tl * BK;
        __syncthreads();   // previous tile's smem readers done

        load_split<BK>(smc, K + ((size_t)b*S_ + kb)*D_, OFF_KH, OFF_KL, 1.0f);
        load_split<BK>(smc, V + ((size_t)b*S_ + kb)*D_, OFF_VH, OFF_VL, 1.0f);
        if (tid < 16) ((unsigned*)(smc + OFF_KPM))[tid] = ((const unsigned*)(kpm + (size_t)b*S_ + kb))[tid];
        __syncthreads();

        // ---- QK^T : scores s[8 n-tiles][4], split-2 (QhKh + QhKl + QlKh) ----
        float s[8][4];
        #pragma unroll
        for (int i = 0; i < 8; ++i)
            #pragma unroll
            for (int j = 0; j < 4; ++j) s[i][j] = 0.0f;

        #pragma unroll
        for (int ks = 0; ks < 8; ++ks) {           // k over D in steps of 16
            const unsigned kbyte = (unsigned)(ks * 32);   // 16 bf16
            unsigned aqh[4], aql[4];
            LDSM_X4(aqh[0], aqh[1], aqh[2], aqh[3], sb + OFF_QH + qrow_off + kbyte);
            LDSM_X4(aql[0], aql[1], aql[2], aql[3], sb + OFF_QL + qrow_off + kbyte);
            #pragma unroll
            for (int np = 0; np < 4; ++np) {       // n-tile pairs: keys np*16
                unsigned roff = (unsigned)(np * 16 * STR) + krow + kbyte;
                unsigned bh0, bh1, bh2, bh3, bl0, bl1, bl2, bl3;
                LDSM_X4(bh0, bh1, bh2, bh3, sb + OFF_KH + roff);
                MMA(s[2*np],   aqh[0], aqh[1], aqh[2], aqh[3], bh0, bh1);
                MMA(s[2*np+1], aqh[0], aqh[1], aqh[2], aqh[3], bh2, bh3);
                MMA(s[2*np],   aql[0], aql[1], aql[2], aql[3], bh0, bh1);
                MMA(s[2*np+1], aql[0], aql[1], aql[2], aql[3], bh2, bh3);
                LDSM_X4(bl0, bl1, bl2, bl3, sb + OFF_KL + roff);
                MMA(s[2*np],   aqh[0], aqh[1], aqh[2], aqh[3], bl0, bl1);
                MMA(s[2*np+1], aqh[0], aqh[1], aqh[2], aqh[3], bl2, bl3);
            }
        }

        // ---- mask + exp + split into P fragments (registers only) ----
        unsigned ph[8][2], pl[8][2];
        const unsigned char* kpms = (const unsigned char*)(smc + OFF_KPM);
        #pragma unroll
        for (int nt = 0; nt < 8; ++nt) {
            const int jl0 = nt*8 + (lane & 3)*2;
            const int jg0 = kb + jl0, jg1 = jg0 + 1;
            const bool kp0 = kpms[jl0] != 0, kp1 = kpms[jl0 + 1] != 0;
            const bool key1_0 = ((jg0 > i1) && (jg0 <= i2)) || (jg0 == 0);
            const bool key1_1 = ((jg1 > i1) && (jg1 <= i2)) || (jg1 == 0);
            const bool key2_0 = ((jg0 > i0) && (jg0 <= i1)) || (jg0 == 0);
            const bool key2_1 = ((jg1 > i0) && (jg1 <= i1)) || (jg1 == 0);

            float v0 = (kp0 || (isr1_0 && key1_0) || (isr2_0 && key2_0)) ? -1e30f : s[nt][0];
            float v1 = (kp1 || (isr1_0 && key1_1) || (isr2_0 && key2_1)) ? -1e30f : s[nt][1];
            float v2 = (kp0 || (isr1_1 && key1_0) || (isr2_1 && key2_0)) ? -1e30f : s[nt][2];
            float v3 = (kp1 || (isr1_1 && key1_1) || (isr2_1 && key2_1)) ? -1e30f : s[nt][3];

            float p0 = __expf(fminf(v0, 60.0f));
            float p1 = __expf(fminf(v1, 60.0f));
            float p2 = __expf(fminf(v2, 60.0f));
            float p3 = __expf(fminf(v3, 60.0f));
            lsum0 += p0 + p1;
            lsum1 += p2 + p3;
            split2(p0, p1, ph[nt][0], pl[nt][0]);
            split2(p2, p3, ph[nt][1], pl[nt][1]);
        }

        // ---- P·V : O += P * V, split-2 (PhVh + PlVh + PhVl) ----
        #pragma unroll
        for (int ks = 0; ks < 4; ++ks) {           // keys in steps of 16
            const unsigned krow_off = (unsigned)(ks * 16 * STR) + vrow;
            const unsigned a0 = ph[2*ks][0], a1 = ph[2*ks][1], a2 = ph[2*ks+1][0], a3 = ph[2*ks+1][1];
            const unsigned c0 = pl[2*ks][0], c1 = pl[2*ks][1], c2 = pl[2*ks+1][0], c3 = pl[2*ks+1][1];
            #pragma unroll
            for (int dp = 0; dp < 8; ++dp) {       // dcol pairs: dcol dp*16
                unsigned off = krow_off + (unsigned)(dp * 32);
                unsigned bh0, bh1, bh2, bh3, bl0, bl1, bl2, bl3;
                LDSM_X4T(bh0, bh1, bh2, bh3, sb + OFF_VH + off);
                MMA(o[2*dp],   a0, a1, a2, a3, bh0, bh1);
                MMA(o[2*dp+1], a0, a1, a2, a3, bh2, bh3);
                MMA(o[2*dp],   c0, c1, c2, c3, bh0, bh1);
                MMA(o[2*dp+1], c0, c1, c2, c3, bh2, bh3);
                LDSM_X4T(bl0, bl1, bl2, bl3, sb + OFF_VL + off);
                MMA(o[2*dp],   a0, a1, a2, a3, bl0, bl1);
                MMA(o[2*dp+1], a0, a1, a2, a3, bl2, bl3);
            }
        }
    }

    // ---- final: reduce l across quad, normalize, store ----
    lsum0 += __shfl_xor_sync(0xffffffffu, lsum0, 1);
    lsum0 += __shfl_xor_sync(0xffffffffu, lsum0, 2);
    lsum1 += __shfl_xor_sync(0xffffffffu, lsum1, 1);
    lsum1 += __shfl_xor_sync(0xffffffffu, lsum1, 2);
    const float inv0 = 1.0f / lsum0;
    const float inv1 = 1.0f / lsum1;

    float* O0 = O + ((size_t)b*S_ + rg0)*D_;
    float* O1 = O + ((size_t)b*S_ + rg1)*D_;
    #pragma unroll
    for (int nt = 0; nt < 16; ++nt) {
        const int col = nt*8 + (lane & 3)*2;
        float2 w0 = make_float2(o[nt][0]*inv0, o[nt][1]*inv0);
        float2 w1 = make_float2(o[nt][2]*inv1, o[nt][3]*inv1);
        *reinterpret_cast<float2*>(O0 + col) = w0;
        *reinterpret_cast<float2*>(O1 + col) = w1;
    }
}

extern "C" void kernel_launch(void* const* d_in, const int* in_sizes, int n_in,
                              void* d_out, int out_size)
{
    const float* Q = (const float*)d_in[0];
    const float* K = (const float*)d_in[1];
    const float* V = (const float*)d_in[2];
    const unsigned char* kpm = (const unsigned char*)d_in[3];
    const int* cls = (const int*)d_in[4];
    float* O = (float*)d_out;

    cudaFuncSetAttribute(fa_mma_kernel, cudaFuncAttributeMaxDynamicSharedMemorySize, SMEM_BYTES);
    dim3 grid(S_/BQ, B_);
    fa_mma_kernel<<<grid, NT, SMEM_BYTES>>>(Q, K, V, kpm, cls, O);
}

// round 9
// speedup vs baseline: 3.4815x; 1.0074x over previous
#include <cuda_runtime.h>
#include <cuda_bf16.h>

#define B_  16
#define S_  2048
#define D_  128
#define BQ  128
#define BK  64
#define NT  256
#define NTILES (S_/BK)

#define STR 272              // smem row stride in bytes (128 bf16 + 8 pad)

#define OFF_QH 0
#define OFF_QL 34816
#define OFF_KH 69632
#define OFF_KL 87040
#define OFF_VH 104448
#define OFF_VL 121856
#define OFF_KPM 139264
#define SMEM_BYTES (139264 + 128)

__device__ __forceinline__ unsigned smem_u32(const void* p) {
    unsigned a;
    asm("{ .reg .u64 t; cvta.to.shared.u64 t, %1; cvt.u32.u64 %0, t; }" : "=r"(a) : "l"(p));
    return a;
}

// Non-volatile (schedulable by ptxas). "memory" clobber on LDSM keeps it
// ordered vs smem stores / barriers, but lets it hoist across MMAs.
#define LDSM_X4(r0,r1,r2,r3,a) \
    asm("ldmatrix.sync.aligned.m8n8.x4.shared.b16 {%0,%1,%2,%3}, [%4];" \
        : "=r"(r0),"=r"(r1),"=r"(r2),"=r"(r3) : "r"(a) : "memory")
#define LDSM_X4T(r0,r1,r2,r3,a) \
    asm("ldmatrix.sync.aligned.m8n8.x4.trans.shared.b16 {%0,%1,%2,%3}, [%4];" \
        : "=r"(r0),"=r"(r1),"=r"(r2),"=r"(r3) : "r"(a) : "memory")

// Pure register dataflow — fully schedulable.
#define MMA(c,a0,a1,a2,a3,b0,b1) \
    asm("mma.sync.aligned.m16n8k16.row.col.f32.bf16.bf16.f32 " \
        "{%0,%1,%2,%3}, {%4,%5,%6,%7}, {%8,%9}, {%0,%1,%2,%3};" \
        : "+f"((c)[0]),"+f"((c)[1]),"+f"((c)[2]),"+f"((c)[3]) \
        : "r"(a0),"r"(a1),"r"(a2),"r"(a3),"r"(b0),"r"(b1))

__device__ __forceinline__ unsigned pack2(float x, float y) {
    __nv_bfloat162 h = __floats2bfloat162_rn(x, y);   // x -> low half
    return *reinterpret_cast<unsigned*>(&h);
}

// split f32 -> (hi bf16, lo bf16) packed pairwise
__device__ __forceinline__ void split2(float x, float y, unsigned& hi, unsigned& lo) {
    __nv_bfloat16 hx = __float2bfloat16(x), hy = __float2bfloat16(y);
    float lx = x - __bfloat162float(hx);
    float ly = y - __bfloat162float(hy);
    __nv_bfloat162 hp; hp.x = hx; hp.y = hy;
    hi = *reinterpret_cast<unsigned*>(&hp);
    lo = pack2(lx, ly);
}

// cooperative load of [rows][128] f32 tile -> split bf16 hi/lo smem (stride 272B)
template<int ROWS>
__device__ __forceinline__ void load_split(char* smc, const float* g, int offH, int offL, float mul) {
    const float4* g4 = reinterpret_cast<const float4*>(g);
    #pragma unroll
    for (int it = 0; it < (ROWS * 32) / NT; ++it) {
        int idx = threadIdx.x + it * NT;
        int r = idx >> 5, c4 = idx & 31;
        float4 v = g4[idx];
        unsigned h0, l0, h1, l1;
        split2(v.x * mul, v.y * mul, h0, l0);
        split2(v.z * mul, v.w * mul, h1, l1);
        unsigned off = (unsigned)(r * STR + c4 * 8);
        *reinterpret_cast<uint2*>(smc + offH + off) = make_uint2(h0, h1);
        *reinterpret_cast<uint2*>(smc + offL + off) = make_uint2(l0, l1);
    }
}

__global__ __launch_bounds__(NT, 1)
void fa_mma_kernel(const float* __restrict__ Q, const float* __restrict__ K,
                   const float* __restrict__ V, const unsigned char* __restrict__ kpm,
                   const int* __restrict__ cls, float* __restrict__ O)
{
    extern __shared__ char smc[];
    const unsigned sb = smem_u32(smc);
    const int tid  = threadIdx.x;
    const int wid  = tid >> 5;
    const int lane = tid & 31;
    const int b  = blockIdx.y;
    const int q0 = blockIdx.x * BQ;

    const int i0 = cls[b*3 + 0];
    const int i1 = cls[b*3 + 1];
    const int i2 = cls[b*3 + 2];

    // this thread's two q-rows (within warp's 16-row block)
    const int rg0 = q0 + wid*16 + (lane >> 2);
    const int rg1 = rg0 + 8;
    const bool isr1_0 = (rg0 == i1), isr2_0 = (rg0 == i2);
    const bool isr1_1 = (rg1 == i1), isr2_1 = (rg1 == i2);

    // Q tile -> smem, pre-scaled by 1/sqrt(d)
    load_split<BQ>(smc, Q + ((size_t)b*S_ + q0)*D_, OFF_QH, OFF_QL, 0.08838834764831845f);

    float o[16][4];
    #pragma unroll
    for (int i = 0; i < 16; ++i)
        #pragma unroll
        for (int j = 0; j < 4; ++j) o[i][j] = 0.0f;
    float lsum0 = 0.0f, lsum1 = 0.0f;

    // per-warp ldmatrix lane addressing (byte offsets within a tile)
    const unsigned qrow_off = (unsigned)((wid*16 + (lane & 15)) * STR) + ((lane >> 4) ? 16u : 0u);
    const unsigned krow     = (unsigned)((((lane >> 4) & 1) * 8 + (lane & 7)) * STR) + (((lane >> 3) & 1) ? 16u : 0u);
    const unsigned vrow     = (unsigned)(((((lane >> 3) & 1) * 8) + (lane & 7)) * STR) + ((lane >> 4) ? 16u : 0u);

    for (int tl = 0; tl < NTILES; ++tl) {
        const int kb = tl * BK;
        __syncthreads();   // previous tile's smem readers done

        load_split<BK>(smc, K + ((size_t)b*S_ + kb)*D_, OFF_KH, OFF_KL, 1.0f);
        load_split<BK>(smc, V + ((size_t)b*S_ + kb)*D_, OFF_VH, OFF_VL, 1.0f);
        if (tid < 16) ((unsigned*)(smc + OFF_KPM))[tid] = ((const unsigned*)(kpm + (size_t)b*S_ + kb))[tid];
        __syncthreads();

        // ---- QK^T : scores s[8 n-tiles][4], split-2 (QhKh + QhKl + QlKh) ----
        float s[8][4];
        #pragma unroll
        for (int i = 0; i < 8; ++i)
            #pragma unroll
            for (int j = 0; j < 4; ++j) s[i][j] = 0.0f;

        #pragma unroll
        for (int ks = 0; ks < 8; ++ks) {           // k over D in steps of 16
            const unsigned kbyte = (unsigned)(ks * 32);   // 16 bf16
            unsigned aqh[4], aql[4];
            LDSM_X4(aqh[0], aqh[1], aqh[2], aqh[3], sb + OFF_QH + qrow_off + kbyte);
            LDSM_X4(aql[0], aql[1], aql[2], aql[3], sb + OFF_QL + qrow_off + kbyte);
            #pragma unroll
            for (int np = 0; np < 4; ++np) {       // n-tile pairs: keys np*16
                unsigned roff = (unsigned)(np * 16 * STR) + krow + kbyte;
                unsigned bh0, bh1, bh2, bh3, bl0, bl1, bl2, bl3;
                LDSM_X4(bh0, bh1, bh2, bh3, sb + OFF_KH + roff);
                MMA(s[2*np],   aqh[0], aqh[1], aqh[2], aqh[3], bh0, bh1);
                MMA(s[2*np+1], aqh[0], aqh[1], aqh[2], aqh[3], bh2, bh3);
                MMA(s[2*np],   aql[0], aql[1], aql[2], aql[3], bh0, bh1);
                MMA(s[2*np+1], aql[0], aql[1], aql[2], aql[3], bh2, bh3);
                LDSM_X4(bl0, bl1, bl2, bl3, sb + OFF_KL + roff);
                MMA(s[2*np],   aqh[0], aqh[1], aqh[2], aqh[3], bl0, bl1);
                MMA(s[2*np+1], aqh[0], aqh[1], aqh[2], aqh[3], bl2, bl3);
            }
        }

        // ---- mask + exp + split into P fragments (registers only) ----
        unsigned ph[8][2], pl[8][2];
        const unsigned char* kpms = (const unsigned char*)(smc + OFF_KPM);
        #pragma unroll
        for (int nt = 0; nt < 8; ++nt) {
            const int jl0 = nt*8 + (lane & 3)*2;
            const int jg0 = kb + jl0, jg1 = jg0 + 1;
            const bool kp0 = kpms[jl0] != 0, kp1 = kpms[jl0 + 1] != 0;
            const bool key1_0 = ((jg0 > i1) && (jg0 <= i2)) || (jg0 == 0);
            const bool key1_1 = ((jg1 > i1) && (jg1 <= i2)) || (jg1 == 0);
            const bool key2_0 = ((jg0 > i0) && (jg0 <= i1)) || (jg0 == 0);
            const bool key2_1 = ((jg1 > i0) && (jg1 <= i1)) || (jg1 == 0);

            float v0 = (kp0 || (isr1_0 && key1_0) || (isr2_0 && key2_0)) ? -1e30f : s[nt][0];
            float v1 = (kp1 || (isr1_0 && key1_1) || (isr2_0 && key2_1)) ? -1e30f : s[nt][1];
            float v2 = (kp0 || (isr1_1 && key1_0) || (isr2_1 && key2_0)) ? -1e30f : s[nt][2];
            float v3 = (kp1 || (isr1_1 && key1_1) || (isr2_1 && key2_1)) ? -1e30f : s[nt][3];

            float p0 = __expf(fminf(v0, 60.0f));
            float p1 = __expf(fminf(v1, 60.0f));
            float p2 = __expf(fminf(v2, 60.0f));
            float p3 = __expf(fminf(v3, 60.0f));
            lsum0 += p0 + p1;
            lsum1 += p2 + p3;
            split2(p0, p1, ph[nt][0], pl[nt][0]);
            split2(p2, p3, ph[nt][1], pl[nt][1]);
        }

        // ---- P·V : O += P * V, split-2 (PhVh + PlVh + PhVl) ----
        #pragma unroll
        for (int ks = 0; ks < 4; ++ks) {           // keys in steps of 16
            const unsigned krow_off = (unsigned)(ks * 16 * STR) + vrow;
            const unsigned a0 = ph[2*ks][0], a1 = ph[2*ks][1], a2 = ph[2*ks+1][0], a3 = ph[2*ks+1][1];
            const unsigned c0 = pl[2*ks][0], c1 = pl[2*ks][1], c2 = pl[2*ks+1][0], c3 = pl[2*ks+1][1];
            #pragma unroll
            for (int dp = 0; dp < 8; ++dp) {       // dcol pairs: dcol dp*16
                unsigned off = krow_off + (unsigned)(dp * 32);
                unsigned bh0, bh1, bh2, bh3, bl0, bl1, bl2, bl3;
                LDSM_X4T(bh0, bh1, bh2, bh3, sb + OFF_VH + off);
                MMA(o[2*dp],   a0, a1, a2, a3, bh0, bh1);
                MMA(o[2*dp+1], a0, a1, a2, a3, bh2, bh3);
                MMA(o[2*dp],   c0, c1, c2, c3, bh0, bh1);
                MMA(o[2*dp+1], c0, c1, c2, c3, bh2, bh3);
                LDSM_X4T(bl0, bl1, bl2, bl3, sb + OFF_VL + off);
                MMA(o[2*dp],   a0, a1, a2, a3, bl0, bl1);
                MMA(o[2*dp+1], a0, a1, a2, a3, bl2, bl3);
            }
        }
    }

    // ---- final: reduce l across quad, normalize, store ----
    lsum0 += __shfl_xor_sync(0xffffffffu, lsum0, 1);
    lsum0 += __shfl_xor_sync(0xffffffffu, lsum0, 2);
    lsum1 += __shfl_xor_sync(0xffffffffu, lsum1, 1);
    lsum1 += __shfl_xor_sync(0xffffffffu, lsum1, 2);
    const float inv0 = 1.0f / lsum0;
    const float inv1 = 1.0f / lsum1;

    float* O0 = O + ((size_t)b*S_ + rg0)*D_;
    float* O1 = O + ((size_t)b*S_ + rg1)*D_;
    #pragma unroll
    for (int nt = 0; nt < 16; ++nt) {
        const int col = nt*8 + (lane & 3)*2;
        float2 w0 = make_float2(o[nt][0]*inv0, o[nt][1]*inv0);
        float2 w1 = make_float2(o[nt][2]*inv1, o[nt][3]*inv1);
        *reinterpret_cast<float2*>(O0 + col) = w0;
        *reinterpret_cast<float2*>(O1 + col) = w1;
    }
}

extern "C" void kernel_launch(void* const* d_in, const int* in_sizes, int n_in,
                              void* d_out, int out_size)
{
    const float* Q = (const float*)d_in[0];
    const float* K = (const float*)d_in[1];
    const float* V = (const float*)d_in[2];
    const unsigned char* kpm = (const unsigned char*)d_in[3];
    const int* cls = (const int*)d_in[4];
    float* O = (float*)d_out;

    cudaFuncSetAttribute(fa_mma_kernel, cudaFuncAttributeMaxDynamicSharedMemorySize, SMEM_BYTES);
    dim3 grid(S_/BQ, B_);
    fa_mma_kernel<<<grid, NT, SMEM_BYTES>>>(Q, K, V, kpm, cls, O);
}